// round 2
// baseline (speedup 1.0000x reference)
#include <cuda_runtime.h>
#include <math.h>

#define NN 100000
#define EE 1600000
#define EN (EE + NN)
#define HH 128
#define DEPTH 9
#define NB_SCAN 98   // ceil(NN/1024)

// ----------------------------- device scratch -------------------------------
__device__ float g_xs[DEPTH][NN * HH];   // skip storage (bn-relu'd layer outputs)
__device__ float g_a[NN * HH];
__device__ float g_b[NN * HH];
__device__ float g_ax[NN * 4];           // 3-wide aggregated x (padded to 4)
__device__ float g_t1[NN];               // 1-wide projected output
__device__ float g_dinv[NN];
__device__ int   g_deg[NN];
__device__ int   g_incl[NN];
__device__ int   g_rowptr[NN];
__device__ int   g_fill[NN];
__device__ int   g_src[EE];
__device__ int   g_dst[EE];
__device__ int   g_col[EN];
__device__ float g_w[EN];
__device__ int   g_blocksum[128];
__device__ int   g_blockoff[128];
__device__ float g_sum[HH], g_sumsq[HH], g_scale[HH], g_shift[HH];
__device__ int   g_is32;

// --------------------------- edge dtype detection ---------------------------
__global__ void detect_dtype_kernel(const unsigned long long* __restrict__ p, int limit) {
    __shared__ int sfound;
    if (threadIdx.x == 0) sfound = 0;
    __syncthreads();
    int found = 0;
    for (int i = threadIdx.x; i < limit; i += blockDim.x)
        if (p[i] > 0xFFFFFFFFull) found = 1;
    if (found) sfound = 1;
    __syncthreads();
    if (threadIdx.x == 0) g_is32 = sfound;
}

__global__ void convert_edges_kernel(const void* __restrict__ raw) {
    int e = blockIdx.x * blockDim.x + threadIdx.x;
    if (e >= EE) return;
    if (g_is32) {
        const int* p = (const int*)raw;
        g_src[e] = p[e];
        g_dst[e] = p[EE + e];
    } else {
        const long long* p = (const long long*)raw;
        g_src[e] = (int)p[e];
        g_dst[e] = (int)p[EE + e];
    }
}

// ------------------------------- CSR build ----------------------------------
__global__ void init_n_kernel() {
    int i = blockIdx.x * blockDim.x + threadIdx.x;
    if (i >= NN) return;
    g_deg[i] = 1;          // self loop
    g_fill[i] = 0;
}

__global__ void deg_count_kernel() {
    int e = blockIdx.x * blockDim.x + threadIdx.x;
    if (e >= EE) return;
    atomicAdd(&g_deg[g_dst[e]], 1);
}

__global__ void dinv_kernel() {
    int i = blockIdx.x * blockDim.x + threadIdx.x;
    if (i >= NN) return;
    g_dinv[i] = rsqrtf((float)g_deg[i]);
}

__global__ void scan1_kernel() {
    __shared__ int sh[1024];
    int tid = threadIdx.x;
    int i = blockIdx.x * 1024 + tid;
    int v = (i < NN) ? g_deg[i] : 0;
    sh[tid] = v;
    __syncthreads();
    for (int off = 1; off < 1024; off <<= 1) {
        int t = (tid >= off) ? sh[tid - off] : 0;
        __syncthreads();
        sh[tid] += t;
        __syncthreads();
    }
    if (i < NN) g_incl[i] = sh[tid];
    if (tid == 1023) g_blocksum[blockIdx.x] = sh[1023];
}

__global__ void scan2_kernel() {
    __shared__ int sh[128];
    int tid = threadIdx.x;
    int v = (tid < NB_SCAN) ? g_blocksum[tid] : 0;
    sh[tid] = v;
    __syncthreads();
    for (int off = 1; off < 128; off <<= 1) {
        int t = (tid >= off) ? sh[tid - off] : 0;
        __syncthreads();
        sh[tid] += t;
        __syncthreads();
    }
    g_blockoff[tid] = sh[tid] - v;  // exclusive
}

__global__ void scan3_kernel() {
    int i = blockIdx.x * blockDim.x + threadIdx.x;
    if (i >= NN) return;
    g_rowptr[i] = g_incl[i] - g_deg[i] + g_blockoff[i >> 10];
}

__global__ void fill_edges_kernel() {
    int e = blockIdx.x * blockDim.x + threadIdx.x;
    if (e >= EE) return;
    int d = g_dst[e];
    int s = g_src[e];
    int pos = g_rowptr[d] + atomicAdd(&g_fill[d], 1);
    g_col[pos] = s;
    g_w[pos] = g_dinv[s] * g_dinv[d];
}

__global__ void fill_self_kernel() {
    int i = blockIdx.x * blockDim.x + threadIdx.x;
    if (i >= NN) return;
    int pos = g_rowptr[i] + atomicAdd(&g_fill[i], 1);
    g_col[pos] = i;
    float dv = g_dinv[i];
    g_w[pos] = dv * dv;
}

// --------------------------- first layer (3-wide) ---------------------------
__global__ void agg3_kernel(const float* __restrict__ x) {
    int gid = blockIdx.x * blockDim.x + threadIdx.x;
    int node = gid >> 5, lane = gid & 31;
    if (node >= NN) return;
    int s0 = g_rowptr[node], cnt = g_deg[node];
    float a0 = 0.f, a1 = 0.f, a2 = 0.f;
    for (int e = s0 + lane; e < s0 + cnt; e += 32) {
        int s = g_col[e];
        float wt = g_w[e];
        a0 += wt * __ldg(&x[s * 3 + 0]);
        a1 += wt * __ldg(&x[s * 3 + 1]);
        a2 += wt * __ldg(&x[s * 3 + 2]);
    }
    for (int off = 16; off; off >>= 1) {
        a0 += __shfl_xor_sync(0xFFFFFFFFu, a0, off);
        a1 += __shfl_xor_sync(0xFFFFFFFFu, a1, off);
        a2 += __shfl_xor_sync(0xFFFFFFFFu, a2, off);
    }
    if (lane == 0) {
        g_ax[node * 4 + 0] = a0;
        g_ax[node * 4 + 1] = a1;
        g_ax[node * 4 + 2] = a2;
    }
}

__global__ void gemm3_kernel(const float* __restrict__ W0, float* __restrict__ out) {
    __shared__ float w[3 * HH];
    for (int i = threadIdx.x; i < 3 * HH; i += blockDim.x) w[i] = W0[i];
    __syncthreads();
    int gid = blockIdx.x * blockDim.x + threadIdx.x;
    int node = gid >> 5, cg = (gid & 31) * 4;
    if (node >= NN) return;
    float a0 = g_ax[node * 4 + 0], a1 = g_ax[node * 4 + 1], a2 = g_ax[node * 4 + 2];
    float4 r;
    r.x = a0 * w[0 * HH + cg + 0] + a1 * w[1 * HH + cg + 0] + a2 * w[2 * HH + cg + 0];
    r.y = a0 * w[0 * HH + cg + 1] + a1 * w[1 * HH + cg + 1] + a2 * w[2 * HH + cg + 1];
    r.z = a0 * w[0 * HH + cg + 2] + a1 * w[1 * HH + cg + 2] + a2 * w[2 * HH + cg + 2];
    r.w = a0 * w[0 * HH + cg + 3] + a1 * w[1 * HH + cg + 3] + a2 * w[2 * HH + cg + 3];
    *(float4*)&out[node * HH + cg] = r;
}

// ------------------------------- 128x128 GEMM -------------------------------
// C[n x 128] = (A1 [+ A2]) @ W[128 x 128]; block tile 128x128, thread tile 8x8.
__global__ void __launch_bounds__(256) gemm128_kernel(
    const float* __restrict__ A1, const float* __restrict__ A2,
    const float* __restrict__ W, float* __restrict__ C, int n)
{
    __shared__ float As[16][132];   // [k][r] transposed, padded
    __shared__ float Ws[16][128];   // [k][c]
    int tx = threadIdx.x & 15, ty = threadIdx.x >> 4;
    int row0 = blockIdx.x * 128;
    float acc[8][8];
    #pragma unroll
    for (int i = 0; i < 8; ++i)
        #pragma unroll
        for (int j = 0; j < 8; ++j) acc[i][j] = 0.f;

    int lr = threadIdx.x >> 2;          // 0..63
    int kq = (threadIdx.x & 3) * 4;     // 0,4,8,12
    int wk = threadIdx.x >> 4;          // 0..15
    int wc = (threadIdx.x & 15) * 8;    // 0..120

    for (int kc = 0; kc < 128; kc += 16) {
        #pragma unroll
        for (int half = 0; half < 2; ++half) {
            int rr = lr + half * 64;
            int grow = row0 + rr;
            float4 v = make_float4(0.f, 0.f, 0.f, 0.f);
            if (grow < n) {
                v = *(const float4*)&A1[grow * HH + kc + kq];
                if (A2) {
                    float4 u = *(const float4*)&A2[grow * HH + kc + kq];
                    v.x += u.x; v.y += u.y; v.z += u.z; v.w += u.w;
                }
            }
            As[kq + 0][rr] = v.x;
            As[kq + 1][rr] = v.y;
            As[kq + 2][rr] = v.z;
            As[kq + 3][rr] = v.w;
        }
        {
            float4 w0 = *(const float4*)&W[(kc + wk) * HH + wc];
            float4 w1 = *(const float4*)&W[(kc + wk) * HH + wc + 4];
            *(float4*)&Ws[wk][wc] = w0;
            *(float4*)&Ws[wk][wc + 4] = w1;
        }
        __syncthreads();
        #pragma unroll
        for (int k = 0; k < 16; ++k) {
            float a[8], b[8];
            *(float4*)&a[0] = *(const float4*)&As[k][ty * 8];
            *(float4*)&a[4] = *(const float4*)&As[k][ty * 8 + 4];
            *(float4*)&b[0] = *(const float4*)&Ws[k][tx * 8];
            *(float4*)&b[4] = *(const float4*)&Ws[k][tx * 8 + 4];
            #pragma unroll
            for (int i = 0; i < 8; ++i)
                #pragma unroll
                for (int j = 0; j < 8; ++j)
                    acc[i][j] += a[i] * b[j];
        }
        __syncthreads();
    }
    #pragma unroll
    for (int i = 0; i < 8; ++i) {
        int grow = row0 + ty * 8 + i;
        if (grow < n) {
            *(float4*)&C[grow * HH + tx * 8]     = *(float4*)&acc[i][0];
            *(float4*)&C[grow * HH + tx * 8 + 4] = *(float4*)&acc[i][4];
        }
    }
}

// ------------------------------ 128-wide aggregate ---------------------------
__global__ void agg128_kernel(const float* __restrict__ hin, float* __restrict__ hout) {
    int gid = blockIdx.x * blockDim.x + threadIdx.x;
    int node = gid >> 5, lane = gid & 31;
    if (node >= NN) return;
    int s0 = g_rowptr[node], cnt = g_deg[node];
    float4 acc = make_float4(0.f, 0.f, 0.f, 0.f);
    for (int e = s0; e < s0 + cnt; ++e) {
        int s = g_col[e];
        float wt = g_w[e];
        float4 v = __ldg((const float4*)&hin[s * HH + lane * 4]);
        acc.x += wt * v.x; acc.y += wt * v.y; acc.z += wt * v.z; acc.w += wt * v.w;
    }
    *(float4*)&hout[node * HH + lane * 4] = acc;
}

// ------------------------------- batch norm ----------------------------------
__global__ void zero_stats_kernel() {
    int c = threadIdx.x;
    g_sum[c] = 0.f;
    g_sumsq[c] = 0.f;
}

__global__ void stats_kernel(const float* __restrict__ in) {
    int c = threadIdx.x & 127;
    int half = threadIdx.x >> 7;
    float s = 0.f, ss = 0.f;
    for (int row = blockIdx.x * 2 + half; row < NN; row += gridDim.x * 2) {
        float v = in[row * HH + c];
        s += v; ss += v * v;
    }
    __shared__ float sh[256], sh2[256];
    sh[threadIdx.x] = s; sh2[threadIdx.x] = ss;
    __syncthreads();
    if (half == 0) {
        s += sh[threadIdx.x + 128];
        ss += sh2[threadIdx.x + 128];
        atomicAdd(&g_sum[c], s);
        atomicAdd(&g_sumsq[c], ss);
    }
}

__global__ void finalize_bn_kernel(const float* __restrict__ gamma, const float* __restrict__ beta) {
    int c = threadIdx.x;
    float m = g_sum[c] / (float)NN;
    float var = g_sumsq[c] / (float)NN - m * m;
    float sc = gamma[c] * rsqrtf(var + 1e-5f);
    g_scale[c] = sc;
    g_shift[c] = beta[c] - m * sc;
}

__global__ void apply_bnrelu_kernel(const float* __restrict__ in, float* __restrict__ out) {
    int gid = blockIdx.x * blockDim.x + threadIdx.x;
    int node = gid >> 5, cg = (gid & 31) * 4;
    if (node >= NN) return;
    float4 v = *(const float4*)&in[node * HH + cg];
    float4 sc = *(const float4*)&g_scale[cg];
    float4 sh = *(const float4*)&g_shift[cg];
    v.x = fmaxf(v.x * sc.x + sh.x, 0.f);
    v.y = fmaxf(v.y * sc.y + sh.y, 0.f);
    v.z = fmaxf(v.z * sc.z + sh.z, 0.f);
    v.w = fmaxf(v.w * sc.w + sh.w, 0.f);
    *(float4*)&out[node * HH + cg] = v;
}

// --------------------------- final projection + agg --------------------------
__global__ void outdot_kernel(const float* __restrict__ cur, const float* __restrict__ skip,
                              const float* __restrict__ Wout) {
    int gid = blockIdx.x * blockDim.x + threadIdx.x;
    int node = gid >> 5, lane = gid & 31;
    if (node >= NN) return;
    float4 a = *(const float4*)&cur[node * HH + lane * 4];
    float4 s = *(const float4*)&skip[node * HH + lane * 4];
    float4 w = __ldg((const float4*)&Wout[lane * 4]);
    float d = (a.x + s.x) * w.x + (a.y + s.y) * w.y + (a.z + s.z) * w.z + (a.w + s.w) * w.w;
    for (int off = 16; off; off >>= 1) d += __shfl_xor_sync(0xFFFFFFFFu, d, off);
    if (lane == 0) g_t1[node] = d;
}

__global__ void agg1_sigmoid_kernel(float* __restrict__ out) {
    int i = blockIdx.x * blockDim.x + threadIdx.x;
    if (i >= NN) return;
    int s0 = g_rowptr[i], cnt = g_deg[i];
    float acc = 0.f;
    for (int e = s0; e < s0 + cnt; ++e)
        acc += g_w[e] * __ldg(&g_t1[g_col[e]]);
    out[i] = 1.f / (1.f + expf(-acc));
}

// ---------------------------------- launch -----------------------------------
static inline float* sym_addr_f(const void* sym) {
    void* p = nullptr;
    cudaGetSymbolAddress(&p, sym);
    return (float*)p;
}

extern "C" void kernel_launch(void* const* d_in, const int* in_sizes, int n_in,
                              void* d_out, int out_size) {
    const float* x    = (const float*)d_in[0];
    const void*  ei   = d_in[1];
    const float* W0   = (const float*)d_in[2];
    const float* Ws1  = (const float*)d_in[3];
    const float* g1   = (const float*)d_in[4];
    const float* b1   = (const float*)d_in[5];
    const float* Ws2  = (const float*)d_in[6];
    const float* g2   = (const float*)d_in[7];
    const float* b2   = (const float*)d_in[8];
    const float* Wout = (const float*)d_in[9];
    float* out = (float*)d_out;

    float* xs = sym_addr_f(g_xs);
    float* pa = sym_addr_f(g_a);
    float* pb = sym_addr_f(g_b);

    const int TB = 256;
    const int gridE  = (EE + TB - 1) / TB;
    const int gridN  = (NN + TB - 1) / TB;
    const int gridNW = (NN * 32 + TB - 1) / TB;   // warp-per-node grids
    const int gridG  = (NN + 127) / 128;          // gemm blocks

    // --- graph build ---
    detect_dtype_kernel<<<1, 256>>>((const unsigned long long*)ei, 2048);
    convert_edges_kernel<<<gridE, TB>>>(ei);
    init_n_kernel<<<gridN, TB>>>();
    deg_count_kernel<<<gridE, TB>>>();
    dinv_kernel<<<gridN, TB>>>();
    scan1_kernel<<<NB_SCAN, 1024>>>();
    scan2_kernel<<<1, 128>>>();
    scan3_kernel<<<gridN, TB>>>();
    fill_edges_kernel<<<gridE, TB>>>();
    fill_self_kernel<<<gridN, TB>>>();

    // --- layer 0: aggregate 3-wide x, then x128 projection, BN+ReLU -> xs[0] ---
    agg3_kernel<<<gridNW, TB>>>(x);
    gemm3_kernel<<<gridNW, TB>>>(W0, pb);
    zero_stats_kernel<<<1, 128>>>();
    stats_kernel<<<256, 256>>>(pb);
    finalize_bn_kernel<<<1, 128>>>(g1, b1);
    apply_bnrelu_kernel<<<gridNW, TB>>>(pb, xs + 0);

    // --- up phase: i = 1..9 ---
    for (int i = 1; i <= DEPTH; ++i) {
        const float* hin = xs + (size_t)(i - 1) * NN * HH;
        gemm128_kernel<<<gridG, 256>>>(hin, nullptr, Ws1 + (size_t)(i - 1) * HH * HH, pa, NN);
        agg128_kernel<<<gridNW, TB>>>(pa, pb);
        zero_stats_kernel<<<1, 128>>>();
        stats_kernel<<<256, 256>>>(pb);
        finalize_bn_kernel<<<1, 128>>>(g1 + (size_t)i * HH, b1 + (size_t)i * HH);
        float* dest = (i < DEPTH) ? (xs + (size_t)i * NN * HH) : pa;
        apply_bnrelu_kernel<<<gridNW, TB>>>(pb, dest);
    }

    // --- down phase: i = 0..7 (cur lives in g_a throughout) ---
    for (int i = 0; i < DEPTH - 1; ++i) {
        int j = DEPTH - 1 - i;
        const float* skip = xs + (size_t)j * NN * HH;
        gemm128_kernel<<<gridG, 256>>>(pa, skip, Ws2 + (size_t)i * HH * HH, pb, NN);
        agg128_kernel<<<gridNW, TB>>>(pb, pa);
        zero_stats_kernel<<<1, 128>>>();
        stats_kernel<<<256, 256>>>(pa);
        finalize_bn_kernel<<<1, 128>>>(g2 + (size_t)i * HH, b2 + (size_t)i * HH);
        apply_bnrelu_kernel<<<gridNW, TB>>>(pa, pa);
    }

    // --- final: (cur + xs[0]) @ Wout, aggregate 1-wide, sigmoid ---
    outdot_kernel<<<gridNW, TB>>>(pa, xs + 0, Wout);
    agg1_sigmoid_kernel<<<gridN, TB>>>(out);
}